// round 6
// baseline (speedup 1.0000x reference)
#include <cuda_runtime.h>

#define DM 64
#define NH 4
#define BB 16
#define TT 1024
#define ROWS_TOTAL (BB*TT)

typedef unsigned long long u64;

__device__ float g_K[ROWS_TOTAL*DM];    // [b,h,t,16]
__device__ float g_V[ROWS_TOTAL*DM];    // [b,h,t,16]
__device__ float g_Q[ROWS_TOTAL*DM];    // [b,h,t,16] (pre-scaled by 0.25*log2e)
__device__ float g_ctx[ROWS_TOTAL*DM];  // [b,t,64]

// ---- packed f32x2 helpers ----
__device__ __forceinline__ u64 pk2(float lo, float hi) {
    u64 d;
    asm("mov.b64 %0,{%1,%2};" : "=l"(d)
        : "r"(__float_as_uint(lo)), "r"(__float_as_uint(hi)));
    return d;
}
__device__ __forceinline__ void up2(u64 d, float& lo, float& hi) {
    unsigned a, b;
    asm("mov.b64 {%0,%1},%2;" : "=r"(a), "=r"(b) : "l"(d));
    lo = __uint_as_float(a); hi = __uint_as_float(b);
}
__device__ __forceinline__ u64 fma2(u64 a, u64 b, u64 c) {
    u64 d;
    asm("fma.rn.f32x2 %0,%1,%2,%3;" : "=l"(d) : "l"(a), "l"(b), "l"(c));
    return d;
}
__device__ __forceinline__ u64 mul2(u64 a, u64 b) {
    u64 d;
    asm("mul.rn.f32x2 %0,%1,%2;" : "=l"(d) : "l"(a), "l"(b));
    return d;
}
__device__ __forceinline__ u64 add2(u64 a, u64 b) {
    u64 d;
    asm("add.rn.f32x2 %0,%1,%2;" : "=l"(d) : "l"(a), "l"(b));
    return d;
}
__device__ __forceinline__ float ex2a(float x) {
    float y;
    asm("ex2.approx.f32 %0,%1;" : "=f"(y) : "f"(x));
    return y;
}

// ---------------------------------------------------------------------------
// Merged KV + Q projections. Blocks [0,256): kv. Blocks [256,512): q.
// ---------------------------------------------------------------------------
__global__ void __launch_bounds__(256) qkv_kernel(const float* __restrict__ x,
                                                  const float* __restrict__ enc,
                                                  const float* __restrict__ Wkv,
                                                  const float* __restrict__ bkv,
                                                  const float* __restrict__ Wq,
                                                  const float* __restrict__ bq) {
    __shared__ float smem[64*64 + 64*128];
    float (*Xs)[64]  = (float(*)[64])smem;
    float (*Ws)[128] = (float(*)[128])(smem + 64*64);
    float (*Wsq)[64] = (float(*)[64])(smem + 64*64);

    if (blockIdx.x < 256) {
        int rowbase = blockIdx.x * 64;
        for (int i = threadIdx.x; i < 64*128/4; i += 256)
            ((float4*)Ws)[i] = ((const float4*)Wkv)[i];
        for (int i = threadIdx.x; i < 64*64/4; i += 256)
            ((float4*)Xs)[i] = ((const float4*)enc)[rowbase*16 + i];
        __syncthreads();

        int c  = threadIdx.x & 127;
        int rg = threadIdx.x >> 7;
        float bias = bkv[c];
        float acc[32];
#pragma unroll
        for (int r = 0; r < 32; r++) acc[r] = bias;
#pragma unroll 4
        for (int k0 = 0; k0 < 64; k0 += 4) {
            float w0 = Ws[k0][c], w1 = Ws[k0+1][c], w2 = Ws[k0+2][c], w3 = Ws[k0+3][c];
#pragma unroll
            for (int r = 0; r < 32; r++) {
                float4 xv = *(const float4*)&Xs[rg*32 + r][k0];
                acc[r] += xv.x*w0 + xv.y*w1 + xv.z*w2 + xv.w*w3;
            }
        }
        int h = (c >> 4) & 3;
        int d = c & 15;
        float* dst = (c < 64) ? g_K : g_V;
#pragma unroll
        for (int r = 0; r < 32; r++) {
            int row = rowbase + rg*32 + r;
            int b = row >> 10, t = row & 1023;
            dst[(((b << 2) | h) * 1024 + t) * 16 + d] = acc[r];
        }
    } else {
        const float QS = 0.25f * 1.4426950408889634f;
        int rowbase = (blockIdx.x - 256) * 64;
        for (int i = threadIdx.x; i < 64*64/4; i += 256) {
            ((float4*)Wsq)[i] = ((const float4*)Wq)[i];
            ((float4*)Xs)[i]  = ((const float4*)x)[rowbase*16 + i];
        }
        __syncthreads();

        int c  = threadIdx.x & 63;
        int rg = threadIdx.x >> 6;
        float bias = bq[c];
        float acc[16];
#pragma unroll
        for (int r = 0; r < 16; r++) acc[r] = bias;
#pragma unroll 4
        for (int k0 = 0; k0 < 64; k0 += 4) {
            float w0 = Wsq[k0][c], w1 = Wsq[k0+1][c], w2 = Wsq[k0+2][c], w3 = Wsq[k0+3][c];
#pragma unroll
            for (int r = 0; r < 16; r++) {
                float4 xv = *(const float4*)&Xs[rg*16 + r][k0];
                acc[r] += xv.x*w0 + xv.y*w1 + xv.z*w2 + xv.w*w3;
            }
        }
        int h = c >> 4;
        int d = c & 15;
#pragma unroll
        for (int r = 0; r < 16; r++) {
            int row = rowbase + rg*16 + r;
            int b = row >> 10, t = row & 1023;
            g_Q[(((b << 2) | h) * 1024 + t) * 16 + d] = acc[r] * QS;
        }
    }
}

// ---------------------------------------------------------------------------
// Attention, single-pass softmax + in-block split-K.
// Block 256 = 8 warps. Warps 0-3: keys [0,512). Warps 4-7: keys [512,1024).
// Both halves process the SAME 256 q rows (2 rows per thread: slot, slot+128).
// Partial (l, acc) of half 1 combined with half 0 via smem (no rescale needed:
// scores bounded |s|<~10, ex2 overflow at 88 -> single-pass softmax exact-safe).
// Smem: phase A (K/V/mask, 34KB) aliased by phase B (partials, 18.4KB).
// ---------------------------------------------------------------------------
__global__ void __launch_bounds__(256) attn_kernel(const int* __restrict__ mask) {
    __shared__ __align__(16) char smraw[34816];
    float* Kbase = (float*)smraw;                 // [2][128][16]
    float* Vbase = (float*)(smraw + 16384);       // [2][128][16]
    u64*   mbb   = (u64*)(smraw + 32768);         // [2][128]
    float* Pl    = (float*)smraw;                 // phase B: [256]
    float* Pacc  = (float*)(smraw + 1024);        // phase B: [256][17]

    int bh  = blockIdx.x;
    int b   = bh >> 2;
    int h   = bh & 3;
    int qt  = blockIdx.y;
    int tid = threadIdx.x;
    int half = tid >> 7;        // 0 or 1 (key-split)
    int lid  = tid & 127;       // row slot

    int r0 = qt*256 + lid;      // rows owned: r0 and r0+128

    u64 qa[8], qb[8];
    {
        const ulonglong2* qp0 = (const ulonglong2*)(g_Q + (bh*1024 + r0) * 16);
        const ulonglong2* qp1 = (const ulonglong2*)(g_Q + (bh*1024 + r0 + 128) * 16);
#pragma unroll
        for (int j = 0; j < 4; j++) {
            ulonglong2 t0 = qp0[j]; qa[2*j] = t0.x; qa[2*j+1] = t0.y;
            ulonglong2 t1 = qp1[j]; qb[2*j] = t1.x; qb[2*j+1] = t1.y;
        }
    }

    float l0 = 0.0f, l1 = 0.0f;
    u64 acc0[8], acc1[8];
#pragma unroll
    for (int j = 0; j < 8; j++) { acc0[j] = 0ull; acc1[j] = 0ull; }

    for (int tile = 0; tile < 4; ++tile) {
        int kb = half*512 + tile*128;
        {
            const float4* kp = (const float4*)(g_K + (bh*1024 + kb + lid) * 16);
            const float4* vp = (const float4*)(g_V + (bh*1024 + kb + lid) * 16);
            float4* ksd = (float4*)(Kbase + (half*128 + lid)*16);
            float4* vsd = (float4*)(Vbase + (half*128 + lid)*16);
            ksd[0]=kp[0]; ksd[1]=kp[1]; ksd[2]=kp[2]; ksd[3]=kp[3];
            vsd[0]=vp[0]; vsd[1]=vp[1]; vsd[2]=vp[2]; vsd[3]=vp[3];
            mbb[half*128 + lid] = pk2(mask[b*1024 + kb + lid] ? 0.0f : -1e30f, 0.0f);
        }
        __syncthreads();

        const float* Kt = Kbase + half*128*16;
        const float* Vt = Vbase + half*128*16;
        const u64*   Mt = mbb + half*128;

#pragma unroll 2
        for (int i = 0; i < 128; i++) {
            const ulonglong2* kr = (const ulonglong2*)(Kt + i*16);
            ulonglong2 k0 = kr[0], k1 = kr[1], k2 = kr[2], k3 = kr[3];
            u64 mbv = Mt[i];
            // row A: two 4-deep chains + add
            u64 eA = fma2(qa[0], k0.x, mbv);
            eA = fma2(qa[1], k0.y, eA); eA = fma2(qa[2], k1.x, eA);
            eA = fma2(qa[3], k1.y, eA);
            u64 fA = mul2(qa[4], k2.x);
            fA = fma2(qa[5], k2.y, fA); fA = fma2(qa[6], k3.x, fA);
            fA = fma2(qa[7], k3.y, fA);
            eA = add2(eA, fA);
            // row B
            u64 eB = fma2(qb[0], k0.x, mbv);
            eB = fma2(qb[1], k0.y, eB); eB = fma2(qb[2], k1.x, eB);
            eB = fma2(qb[3], k1.y, eB);
            u64 fB = mul2(qb[4], k2.x);
            fB = fma2(qb[5], k2.y, fB); fB = fma2(qb[6], k3.x, fB);
            fB = fma2(qb[7], k3.y, fB);
            eB = add2(eB, fB);

            float lo, hi;
            up2(eA, lo, hi); float p0 = ex2a(lo + hi);
            up2(eB, lo, hi); float p1 = ex2a(lo + hi);
            l0 += p0; l1 += p1;
            u64 pd0 = pk2(p0, p0), pd1 = pk2(p1, p1);

            const ulonglong2* vr = (const ulonglong2*)(Vt + i*16);
            ulonglong2 v0 = vr[0], v1 = vr[1], v2 = vr[2], v3 = vr[3];
            acc0[0] = fma2(pd0, v0.x, acc0[0]); acc0[1] = fma2(pd0, v0.y, acc0[1]);
            acc0[2] = fma2(pd0, v1.x, acc0[2]); acc0[3] = fma2(pd0, v1.y, acc0[3]);
            acc0[4] = fma2(pd0, v2.x, acc0[4]); acc0[5] = fma2(pd0, v2.y, acc0[5]);
            acc0[6] = fma2(pd0, v3.x, acc0[6]); acc0[7] = fma2(pd0, v3.y, acc0[7]);
            acc1[0] = fma2(pd1, v0.x, acc1[0]); acc1[1] = fma2(pd1, v0.y, acc1[1]);
            acc1[2] = fma2(pd1, v1.x, acc1[2]); acc1[3] = fma2(pd1, v1.y, acc1[3]);
            acc1[4] = fma2(pd1, v2.x, acc1[4]); acc1[5] = fma2(pd1, v2.y, acc1[5]);
            acc1[6] = fma2(pd1, v3.x, acc1[6]); acc1[7] = fma2(pd1, v3.y, acc1[7]);
        }
        __syncthreads();
    }

    // ---- phase B: half 1 publishes partials into aliased smem ----
    if (half) {
        Pl[lid]       = l0;
        Pl[lid + 128] = l1;
        float* pa0 = Pacc + lid*17;
        float* pa1 = Pacc + (lid + 128)*17;
#pragma unroll
        for (int j = 0; j < 8; j++) {
            float lo, hi;
            up2(acc0[j], lo, hi); pa0[2*j] = lo; pa0[2*j+1] = hi;
            up2(acc1[j], lo, hi); pa1[2*j] = lo; pa1[2*j+1] = hi;
        }
    }
    __syncthreads();

    // ---- half 0 combines and writes both its rows ----
    if (!half) {
        {
            float inv = 1.0f / (l0 + Pl[lid]);
            const float* pa = Pacc + lid*17;
            float o[16];
#pragma unroll
            for (int j = 0; j < 8; j++) {
                float lo, hi;
                up2(acc0[j], lo, hi);
                o[2*j]   = (lo + pa[2*j])   * inv;
                o[2*j+1] = (hi + pa[2*j+1]) * inv;
            }
            float4* o4 = (float4*)(g_ctx + (b*1024 + r0) * 64 + h*16);
            o4[0] = make_float4(o[0],  o[1],  o[2],  o[3]);
            o4[1] = make_float4(o[4],  o[5],  o[6],  o[7]);
            o4[2] = make_float4(o[8],  o[9],  o[10], o[11]);
            o4[3] = make_float4(o[12], o[13], o[14], o[15]);
        }
        {
            float inv = 1.0f / (l1 + Pl[lid + 128]);
            const float* pa = Pacc + (lid + 128)*17;
            float o[16];
#pragma unroll
            for (int j = 0; j < 8; j++) {
                float lo, hi;
                up2(acc1[j], lo, hi);
                o[2*j]   = (lo + pa[2*j])   * inv;
                o[2*j+1] = (hi + pa[2*j+1]) * inv;
            }
            float4* o4 = (float4*)(g_ctx + (b*1024 + r0 + 128) * 64 + h*16);
            o4[0] = make_float4(o[0],  o[1],  o[2],  o[3]);
            o4[1] = make_float4(o[4],  o[5],  o[6],  o[7]);
            o4[2] = make_float4(o[8],  o[9],  o[10], o[11]);
            o4[3] = make_float4(o[12], o[13], o[14], o[15]);
        }
    }
}

// ---------------------------------------------------------------------------
// Output projection.
// ---------------------------------------------------------------------------
__global__ void __launch_bounds__(256) proj_kernel(const float* __restrict__ Wp,
                                                   const float* __restrict__ bp,
                                                   float* __restrict__ out) {
    __shared__ float Xs[64][64];
    __shared__ float Ws[64][64];
    int rowbase = blockIdx.x * 64;

    for (int i = threadIdx.x; i < 64*64/4; i += 256) {
        ((float4*)Ws)[i] = ((const float4*)Wp)[i];
        ((float4*)Xs)[i] = ((const float4*)g_ctx)[rowbase*16 + i];
    }
    __syncthreads();

    int c  = threadIdx.x & 63;
    int rg = threadIdx.x >> 6;
    float bias = bp[c];
    float acc[16];
#pragma unroll
    for (int r = 0; r < 16; r++) acc[r] = bias;
#pragma unroll 4
    for (int k0 = 0; k0 < 64; k0 += 4) {
        float w0 = Ws[k0][c], w1 = Ws[k0+1][c], w2 = Ws[k0+2][c], w3 = Ws[k0+3][c];
#pragma unroll
        for (int r = 0; r < 16; r++) {
            float4 xv = *(const float4*)&Xs[rg*16 + r][k0];
            acc[r] += xv.x*w0 + xv.y*w1 + xv.z*w2 + xv.w*w3;
        }
    }
#pragma unroll
    for (int r = 0; r < 16; r++)
        out[(rowbase + rg*16 + r) * 64 + c] = acc[r];
}

// ---------------------------------------------------------------------------
extern "C" void kernel_launch(void* const* d_in, const int* in_sizes, int n_in,
                              void* d_out, int out_size) {
    const float* x    = (const float*)d_in[0];
    const float* enc  = (const float*)d_in[1];
    const int*   msk  = (const int*)  d_in[2];
    const float* Wkv  = (const float*)d_in[3];
    const float* bkv  = (const float*)d_in[4];
    const float* Wq   = (const float*)d_in[5];
    const float* bq   = (const float*)d_in[6];
    const float* Wp   = (const float*)d_in[7];
    const float* bp   = (const float*)d_in[8];
    float* out = (float*)d_out;

    qkv_kernel<<<512, 256>>>(x, enc, Wkv, bkv, Wq, bq);
    attn_kernel<<<dim3(BB*NH, TT/256), 256>>>(msk);
    proj_kernel<<<ROWS_TOTAL/64, 256>>>(Wp, bp, out);
}

// round 7
// speedup vs baseline: 1.6674x; 1.6674x over previous
#include <cuda_runtime.h>

#define DM 64
#define NH 4
#define BB 16
#define TT 1024
#define ROWS_TOTAL (BB*TT)

typedef unsigned long long u64;

__device__ float g_K[ROWS_TOTAL*DM];    // [b,h,t,16]
__device__ float g_V[ROWS_TOTAL*DM];    // [b,h,t,16]
__device__ float g_Q[ROWS_TOTAL*DM];    // [b,h,t,16] (pre-scaled by 0.25*log2e)
__device__ float g_ctx[ROWS_TOTAL*DM];  // [b,t,64]

// ---- packed f32x2 helpers ----
__device__ __forceinline__ u64 pk2(float lo, float hi) {
    u64 d;
    asm("mov.b64 %0,{%1,%2};" : "=l"(d)
        : "r"(__float_as_uint(lo)), "r"(__float_as_uint(hi)));
    return d;
}
__device__ __forceinline__ void up2(u64 d, float& lo, float& hi) {
    unsigned a, b;
    asm("mov.b64 {%0,%1},%2;" : "=r"(a), "=r"(b) : "l"(d));
    lo = __uint_as_float(a); hi = __uint_as_float(b);
}
__device__ __forceinline__ u64 fma2(u64 a, u64 b, u64 c) {
    u64 d;
    asm("fma.rn.f32x2 %0,%1,%2,%3;" : "=l"(d) : "l"(a), "l"(b), "l"(c));
    return d;
}
__device__ __forceinline__ u64 mul2(u64 a, u64 b) {
    u64 d;
    asm("mul.rn.f32x2 %0,%1,%2;" : "=l"(d) : "l"(a), "l"(b));
    return d;
}
__device__ __forceinline__ float ex2a(float x) {
    float y;
    asm("ex2.approx.f32 %0,%1;" : "=f"(y) : "f"(x));
    return y;
}

// ---------------------------------------------------------------------------
// Merged KV + Q projections. Blocks [0,256): kv. Blocks [256,512): q.
// ---------------------------------------------------------------------------
__global__ void __launch_bounds__(256) qkv_kernel(const float* __restrict__ x,
                                                  const float* __restrict__ enc,
                                                  const float* __restrict__ Wkv,
                                                  const float* __restrict__ bkv,
                                                  const float* __restrict__ Wq,
                                                  const float* __restrict__ bq) {
    __shared__ float smem[64*64 + 64*128];
    float (*Xs)[64]  = (float(*)[64])smem;
    float (*Ws)[128] = (float(*)[128])(smem + 64*64);
    float (*Wsq)[64] = (float(*)[64])(smem + 64*64);

    if (blockIdx.x < 256) {
        int rowbase = blockIdx.x * 64;
        for (int i = threadIdx.x; i < 64*128/4; i += 256)
            ((float4*)Ws)[i] = ((const float4*)Wkv)[i];
        for (int i = threadIdx.x; i < 64*64/4; i += 256)
            ((float4*)Xs)[i] = ((const float4*)enc)[rowbase*16 + i];
        __syncthreads();

        int c  = threadIdx.x & 127;
        int rg = threadIdx.x >> 7;
        float bias = bkv[c];
        float acc[32];
#pragma unroll
        for (int r = 0; r < 32; r++) acc[r] = bias;
#pragma unroll 4
        for (int k0 = 0; k0 < 64; k0 += 4) {
            float w0 = Ws[k0][c], w1 = Ws[k0+1][c], w2 = Ws[k0+2][c], w3 = Ws[k0+3][c];
#pragma unroll
            for (int r = 0; r < 32; r++) {
                float4 xv = *(const float4*)&Xs[rg*32 + r][k0];
                acc[r] += xv.x*w0 + xv.y*w1 + xv.z*w2 + xv.w*w3;
            }
        }
        int h = (c >> 4) & 3;
        int d = c & 15;
        float* dst = (c < 64) ? g_K : g_V;
#pragma unroll
        for (int r = 0; r < 32; r++) {
            int row = rowbase + rg*32 + r;
            int b = row >> 10, t = row & 1023;
            dst[(((b << 2) | h) * 1024 + t) * 16 + d] = acc[r];
        }
    } else {
        const float QS = 0.25f * 1.4426950408889634f;
        int rowbase = (blockIdx.x - 256) * 64;
        for (int i = threadIdx.x; i < 64*64/4; i += 256) {
            ((float4*)Wsq)[i] = ((const float4*)Wq)[i];
            ((float4*)Xs)[i]  = ((const float4*)x)[rowbase*16 + i];
        }
        __syncthreads();

        int c  = threadIdx.x & 63;
        int rg = threadIdx.x >> 6;
        float bias = bq[c];
        float acc[16];
#pragma unroll
        for (int r = 0; r < 16; r++) acc[r] = bias;
#pragma unroll 4
        for (int k0 = 0; k0 < 64; k0 += 4) {
            float w0 = Wsq[k0][c], w1 = Wsq[k0+1][c], w2 = Wsq[k0+2][c], w3 = Wsq[k0+3][c];
#pragma unroll
            for (int r = 0; r < 16; r++) {
                float4 xv = *(const float4*)&Xs[rg*16 + r][k0];
                acc[r] += xv.x*w0 + xv.y*w1 + xv.z*w2 + xv.w*w3;
            }
        }
        int h = c >> 4;
        int d = c & 15;
#pragma unroll
        for (int r = 0; r < 16; r++) {
            int row = rowbase + rg*16 + r;
            int b = row >> 10, t = row & 1023;
            g_Q[(((b << 2) | h) * 1024 + t) * 16 + d] = acc[r] * QS;
        }
    }
}

// ---------------------------------------------------------------------------
// Attention: single-pass softmax + in-block split-K, straight 8-deep chains.
// Block 256 = 8 warps. Warps 0-3: keys [0,512). Warps 4-7: keys [512,1024).
// Both halves process the SAME 256 q rows (2 rows/thread: slot, slot+128).
// Partials combined through smem (exact: no rescale needed, |s| < ~10 << 88).
// ---------------------------------------------------------------------------
__global__ void __launch_bounds__(256) attn_kernel(const int* __restrict__ mask) {
    __shared__ __align__(16) char smraw[34816];
    float* Kbase = (float*)smraw;                 // [2][128][16]
    float* Vbase = (float*)(smraw + 16384);       // [2][128][16]
    u64*   mbb   = (u64*)(smraw + 32768);         // [2][128]
    float* Pl    = (float*)smraw;                 // phase B: [256]
    float* Pacc  = (float*)(smraw + 1024);        // phase B: [256][17]

    int bh  = blockIdx.x;
    int b   = bh >> 2;
    int h   = bh & 3;
    int qt  = blockIdx.y;
    int tid = threadIdx.x;
    int half = tid >> 7;        // key-split half
    int lid  = tid & 127;       // row slot

    int r0 = qt*256 + lid;      // rows owned: r0, r0+128

    u64 qa[8], qb[8];
    {
        const ulonglong2* qp0 = (const ulonglong2*)(g_Q + (bh*1024 + r0) * 16);
        const ulonglong2* qp1 = (const ulonglong2*)(g_Q + (bh*1024 + r0 + 128) * 16);
#pragma unroll
        for (int j = 0; j < 4; j++) {
            ulonglong2 t0 = qp0[j]; qa[2*j] = t0.x; qa[2*j+1] = t0.y;
            ulonglong2 t1 = qp1[j]; qb[2*j] = t1.x; qb[2*j+1] = t1.y;
        }
    }

    float l0 = 0.0f, l1 = 0.0f;
    u64 acc0[8], acc1[8];
#pragma unroll
    for (int j = 0; j < 8; j++) { acc0[j] = 0ull; acc1[j] = 0ull; }

    for (int tile = 0; tile < 4; ++tile) {
        int kb = half*512 + tile*128;
        {
            const float4* kp = (const float4*)(g_K + (bh*1024 + kb + lid) * 16);
            const float4* vp = (const float4*)(g_V + (bh*1024 + kb + lid) * 16);
            float4* ksd = (float4*)(Kbase + (half*128 + lid)*16);
            float4* vsd = (float4*)(Vbase + (half*128 + lid)*16);
            ksd[0]=kp[0]; ksd[1]=kp[1]; ksd[2]=kp[2]; ksd[3]=kp[3];
            vsd[0]=vp[0]; vsd[1]=vp[1]; vsd[2]=vp[2]; vsd[3]=vp[3];
            mbb[half*128 + lid] = pk2(mask[b*1024 + kb + lid] ? 0.0f : -1e30f, 0.0f);
        }
        __syncthreads();

        const float* Kt = Kbase + half*128*16;
        const float* Vt = Vbase + half*128*16;
        const u64*   Mt = mbb + half*128;

#pragma unroll 2
        for (int i = 0; i < 128; i++) {
            const ulonglong2* kr = (const ulonglong2*)(Kt + i*16);
            ulonglong2 k0 = kr[0], k1 = kr[1], k2 = kr[2], k3 = kr[3];
            u64 mbv = Mt[i];
            u64 eA = fma2(qa[0], k0.x, mbv);
            eA = fma2(qa[1], k0.y, eA); eA = fma2(qa[2], k1.x, eA);
            eA = fma2(qa[3], k1.y, eA); eA = fma2(qa[4], k2.x, eA);
            eA = fma2(qa[5], k2.y, eA); eA = fma2(qa[6], k3.x, eA);
            eA = fma2(qa[7], k3.y, eA);
            u64 eB = fma2(qb[0], k0.x, mbv);
            eB = fma2(qb[1], k0.y, eB); eB = fma2(qb[2], k1.x, eB);
            eB = fma2(qb[3], k1.y, eB); eB = fma2(qb[4], k2.x, eB);
            eB = fma2(qb[5], k2.y, eB); eB = fma2(qb[6], k3.x, eB);
            eB = fma2(qb[7], k3.y, eB);

            float lo, hi;
            up2(eA, lo, hi); float p0 = ex2a(lo + hi);
            up2(eB, lo, hi); float p1 = ex2a(lo + hi);
            l0 += p0; l1 += p1;
            u64 pd0 = pk2(p0, p0), pd1 = pk2(p1, p1);

            const ulonglong2* vr = (const ulonglong2*)(Vt + i*16);
            ulonglong2 v0 = vr[0], v1 = vr[1], v2 = vr[2], v3 = vr[3];
            acc0[0] = fma2(pd0, v0.x, acc0[0]); acc0[1] = fma2(pd0, v0.y, acc0[1]);
            acc0[2] = fma2(pd0, v1.x, acc0[2]); acc0[3] = fma2(pd0, v1.y, acc0[3]);
            acc0[4] = fma2(pd0, v2.x, acc0[4]); acc0[5] = fma2(pd0, v2.y, acc0[5]);
            acc0[6] = fma2(pd0, v3.x, acc0[6]); acc0[7] = fma2(pd0, v3.y, acc0[7]);
            acc1[0] = fma2(pd1, v0.x, acc1[0]); acc1[1] = fma2(pd1, v0.y, acc1[1]);
            acc1[2] = fma2(pd1, v1.x, acc1[2]); acc1[3] = fma2(pd1, v1.y, acc1[3]);
            acc1[4] = fma2(pd1, v2.x, acc1[4]); acc1[5] = fma2(pd1, v2.y, acc1[5]);
            acc1[6] = fma2(pd1, v3.x, acc1[6]); acc1[7] = fma2(pd1, v3.y, acc1[7]);
        }
        __syncthreads();
    }

    // ---- phase B: half 1 publishes partials into aliased smem ----
    if (half) {
        Pl[lid]       = l0;
        Pl[lid + 128] = l1;
        float* pa0 = Pacc + lid*17;
        float* pa1 = Pacc + (lid + 128)*17;
#pragma unroll
        for (int j = 0; j < 8; j++) {
            float lo, hi;
            up2(acc0[j], lo, hi); pa0[2*j] = lo; pa0[2*j+1] = hi;
            up2(acc1[j], lo, hi); pa1[2*j] = lo; pa1[2*j+1] = hi;
        }
    }
    __syncthreads();

    // ---- half 0 combines and writes both rows ----
    if (!half) {
        {
            float inv = 1.0f / (l0 + Pl[lid]);
            const float* pa = Pacc + lid*17;
            float o[16];
#pragma unroll
            for (int j = 0; j < 8; j++) {
                float lo, hi;
                up2(acc0[j], lo, hi);
                o[2*j]   = (lo + pa[2*j])   * inv;
                o[2*j+1] = (hi + pa[2*j+1]) * inv;
            }
            float4* o4 = (float4*)(g_ctx + (b*1024 + r0) * 64 + h*16);
            o4[0] = make_float4(o[0],  o[1],  o[2],  o[3]);
            o4[1] = make_float4(o[4],  o[5],  o[6],  o[7]);
            o4[2] = make_float4(o[8],  o[9],  o[10], o[11]);
            o4[3] = make_float4(o[12], o[13], o[14], o[15]);
        }
        {
            float inv = 1.0f / (l1 + Pl[lid + 128]);
            const float* pa = Pacc + (lid + 128)*17;
            float o[16];
#pragma unroll
            for (int j = 0; j < 8; j++) {
                float lo, hi;
                up2(acc1[j], lo, hi);
                o[2*j]   = (lo + pa[2*j])   * inv;
                o[2*j+1] = (hi + pa[2*j+1]) * inv;
            }
            float4* o4 = (float4*)(g_ctx + (b*1024 + r0 + 128) * 64 + h*16);
            o4[0] = make_float4(o[0],  o[1],  o[2],  o[3]);
            o4[1] = make_float4(o[4],  o[5],  o[6],  o[7]);
            o4[2] = make_float4(o[8],  o[9],  o[10], o[11]);
            o4[3] = make_float4(o[12], o[13], o[14], o[15]);
        }
    }
}

// ---------------------------------------------------------------------------
// Output projection.
// ---------------------------------------------------------------------------
__global__ void __launch_bounds__(256) proj_kernel(const float* __restrict__ Wp,
                                                   const float* __restrict__ bp,
                                                   float* __restrict__ out) {
    __shared__ float Xs[64][64];
    __shared__ float Ws[64][64];
    int rowbase = blockIdx.x * 64;

    for (int i = threadIdx.x; i < 64*64/4; i += 256) {
        ((float4*)Ws)[i] = ((const float4*)Wp)[i];
        ((float4*)Xs)[i] = ((const float4*)g_ctx)[rowbase*16 + i];
    }
    __syncthreads();

    int c  = threadIdx.x & 63;
    int rg = threadIdx.x >> 6;
    float bias = bp[c];
    float acc[16];
#pragma unroll
    for (int r = 0; r < 16; r++) acc[r] = bias;
#pragma unroll 4
    for (int k0 = 0; k0 < 64; k0 += 4) {
        float w0 = Ws[k0][c], w1 = Ws[k0+1][c], w2 = Ws[k0+2][c], w3 = Ws[k0+3][c];
#pragma unroll
        for (int r = 0; r < 16; r++) {
            float4 xv = *(const float4*)&Xs[rg*16 + r][k0];
            acc[r] += xv.x*w0 + xv.y*w1 + xv.z*w2 + xv.w*w3;
        }
    }
#pragma unroll
    for (int r = 0; r < 16; r++)
        out[(rowbase + rg*16 + r) * 64 + c] = acc[r];
}

// ---------------------------------------------------------------------------
extern "C" void kernel_launch(void* const* d_in, const int* in_sizes, int n_in,
                              void* d_out, int out_size) {
    const float* x    = (const float*)d_in[0];
    const float* enc  = (const float*)d_in[1];
    const int*   msk  = (const int*)  d_in[2];
    const float* Wkv  = (const float*)d_in[3];
    const float* bkv  = (const float*)d_in[4];
    const float* Wq   = (const float*)d_in[5];
    const float* bq   = (const float*)d_in[6];
    const float* Wp   = (const float*)d_in[7];
    const float* bp   = (const float*)d_in[8];
    float* out = (float*)d_out;

    qkv_kernel<<<512, 256>>>(x, enc, Wkv, bkv, Wq, bq);
    attn_kernel<<<dim3(BB*NH, TT/256), 256>>>(msk);
    proj_kernel<<<ROWS_TOTAL/64, 256>>>(Wp, bp, out);
}